// round 3
// baseline (speedup 1.0000x reference)
#include <cuda_runtime.h>
#include <cstdint>

#define EPSF 1e-6f
#define G_ 3
#define S_ 10
#define N_ 5000
#define K_ 20
#define O_ 1000
#define ROWS_G (S_*N_)            /* 50000 rows per g */
#define NT 256                    /* threads per block */
#define RPT 4                     /* rows per thread */
#define TR (NT*RPT)               /* 1024 rows per block tile */
#define TO 8                      /* o's per stage */
#define RS 10                     /* padded row stride (floats) in counts tile */
#define NSTAGE (O_/TO)            /* 125 */
#define NTILES ((ROWS_G + TR - 1)/TR)   /* 49 */
#define NBLOCKS (NTILES*G_)             /* 147 */
#define SH_LM_FLOATS (O_*K_)            /* 20000 */
#define SH_TILE_FLOATS (TR*RS)          /* 10240 */
#define SMEM_BYTES ((SH_LM_FLOATS + 2*SH_TILE_FLOATS)*4)  /* 161920 */

__device__ float g_lm[G_*O_*K_];     // [g][o][k]  log(mix+eps)
__device__ float g_bias[G_*S_*K_];   // [g][s][k]  log(comm_dist+eps)
__device__ float g_part[NBLOCKS];

// ---------------- prep: log_mix + bias ----------------
__global__ void prep_kernel(const float* __restrict__ otu,   // [K][O]
                            const float* __restrict__ comm,  // [K][G][S]
                            const float* __restrict__ cwv,   // [G]
                            const float* __restrict__ ccm) { // [G][O]
    int idx = blockIdx.x * blockDim.x + threadIdx.x;
    if (idx < G_*O_*K_) {
        int g = idx / (O_*K_);
        int rem = idx - g*(O_*K_);
        int o = rem / K_;
        int k = rem - o*K_;
        float cw = cwv[g];
        float mix = otu[k*O_ + o] * (1.0f - cw) + cw * ccm[g*O_ + o];
        g_lm[idx] = logf(mix + EPSF);
    }
    if (idx < G_*S_*K_) {
        int g = idx / (S_*K_);
        int r2 = idx - g*(S_*K_);
        int s = r2 / K_;
        int k = r2 - s*K_;
        g_bias[idx] = logf(comm[k*(G_*S_) + g*S_ + s] + EPSF);
    }
}

// ---------------- helpers ----------------
__device__ __forceinline__ unsigned long long ffma2(unsigned long long a,
                                                    unsigned long long b,
                                                    unsigned long long c) {
    unsigned long long d;
    asm("fma.rn.f32x2 %0, %1, %2, %3;" : "=l"(d) : "l"(a), "l"(b), "l"(c));
    return d;
}
__device__ __forceinline__ unsigned long long pack2(float x) {
    unsigned long long d;
    unsigned int u = __float_as_uint(x);
    asm("mov.b64 %0, {%1, %1};" : "=l"(d) : "r"(u));
    return d;
}
__device__ __forceinline__ void cpa8(float* dst, const float* src) {
    unsigned int d = (unsigned int)__cvta_generic_to_shared(dst);
    asm volatile("cp.async.ca.shared.global [%0], [%1], 8;" :: "r"(d), "l"(src));
}

// ---------------- main: scores + LSE, fused ----------------
__global__ void __launch_bounds__(NT, 1)
score_kernel(const float* __restrict__ counts, const float* __restrict__ gamma_p) {
    extern __shared__ float sh[];
    float* sh_lm = sh;                      // [O_][K_]
    float* sh_t  = sh + SH_LM_FLOATS;       // [2][TR][RS]

    const int g = blockIdx.y;
    const long row_base = (long)blockIdx.x * TR;
    const float* cptr = counts + (long)g * ROWS_G * O_;
    const int t = threadIdx.x;

    // load log_mix[g] into smem (coalesced float4)
    {
        const float4* src = (const float4*)(g_lm + g*(O_*K_));
        float4* dst = (float4*)sh_lm;
        #pragma unroll 4
        for (int i = t; i < SH_LM_FLOATS/4; i += NT) dst[i] = src[i];
    }

    // stage 0
    {
        float* dst = sh_t;
        #pragma unroll
        for (int it = 0; it < (TR*4)/NT; it++) {
            int c = t + it*NT;
            int r = c >> 2, j = c & 3;
            long grow = row_base + r;
            if (grow < ROWS_G)
                cpa8(dst + r*RS + j*2, cptr + grow*(long)O_ + j*2);
        }
        asm volatile("cp.async.commit_group;" ::: "memory");
    }
    asm volatile("cp.async.wait_group 0;" ::: "memory");
    __syncthreads();

    unsigned long long acc[RPT][10];
    #pragma unroll
    for (int i = 0; i < RPT; i++)
        #pragma unroll
        for (int p = 0; p < 10; p++) acc[i][p] = 0ULL;

    for (int st = 0; st < NSTAGE; st++) {
        const int b = st & 1;
        // issue next stage into the other buffer (safe: readers of it synced last iter)
        if (st + 1 < NSTAGE) {
            float* dst = sh_t + (b ^ 1) * SH_TILE_FLOATS;
            const int ob = (st + 1) * TO;
            #pragma unroll
            for (int it = 0; it < (TR*4)/NT; it++) {
                int c = t + it*NT;
                int r = c >> 2, j = c & 3;
                long grow = row_base + r;
                if (grow < ROWS_G)
                    cpa8(dst + r*RS + j*2, cptr + grow*(long)O_ + ob + j*2);
            }
        }
        asm volatile("cp.async.commit_group;" ::: "memory");

        // compute current buffer
        const float* tb = sh_t + b * SH_TILE_FLOATS;
        #pragma unroll
        for (int oo = 0; oo < TO; oo++) {
            const int o = st*TO + oo;
            const ulonglong2* lr = (const ulonglong2*)(sh_lm + o*K_); // 80B row, 16B aligned
            unsigned long long Lp[10];
            {
                ulonglong2 v0 = lr[0], v1 = lr[1], v2 = lr[2], v3 = lr[3], v4 = lr[4];
                Lp[0]=v0.x; Lp[1]=v0.y; Lp[2]=v1.x; Lp[3]=v1.y; Lp[4]=v2.x;
                Lp[5]=v2.y; Lp[6]=v3.x; Lp[7]=v3.y; Lp[8]=v4.x; Lp[9]=v4.y;
            }
            #pragma unroll
            for (int i = 0; i < RPT; i++) {
                float c = tb[(t + i*NT)*RS + oo];
                unsigned long long cc = pack2(c);
                #pragma unroll
                for (int p = 0; p < 10; p++)
                    acc[i][p] = ffma2(cc, Lp[p], acc[i][p]);
            }
        }

        asm volatile("cp.async.wait_group 0;" ::: "memory");
        __syncthreads();
    }

    // ---- epilogue: bias + LSE per row ----
    const float gam = *gamma_p;
    float lsum = 0.0f;
    #pragma unroll
    for (int i = 0; i < RPT; i++) {
        long grow = row_base + t + i*NT;
        if (grow < ROWS_G) {
            int srow = (int)(grow / N_);
            const float* bptr = g_bias + g*(S_*K_) + srow*K_;
            float sc[K_];
            #pragma unroll
            for (int p = 0; p < 10; p++) {
                unsigned long long v = acc[i][p];
                float lo = __uint_as_float((unsigned int)(v & 0xffffffffULL));
                float hi = __uint_as_float((unsigned int)(v >> 32));
                sc[2*p]   = lo + bptr[2*p];
                sc[2*p+1] = hi + bptr[2*p+1];
            }
            float m = sc[0];
            #pragma unroll
            for (int k = 1; k < K_; k++) m = fmaxf(m, sc[k]);
            float ssum = 0.0f;
            #pragma unroll
            for (int k = 0; k < K_; k++) ssum += __expf(gam * (sc[k] - m));
            lsum += m + __logf(ssum);
        }
    }

    // deterministic block reduction
    #pragma unroll
    for (int o = 16; o > 0; o >>= 1) lsum += __shfl_xor_sync(0xffffffffu, lsum, o);
    __shared__ float red[NT/32];
    const int w = t >> 5;
    if ((t & 31) == 0) red[w] = lsum;
    __syncthreads();
    if (t < NT/32) {
        float v = red[t];
        #pragma unroll
        for (int o = (NT/64); o > 0; o >>= 1) v += __shfl_xor_sync(0xffu, v, o);
        if (t == 0) g_part[blockIdx.y * NTILES + blockIdx.x] = v;
    }
}

// ---------------- finalize: deterministic sum of partials ----------------
__global__ void fin_kernel(float* out) {
    float s = 0.0f;
    for (int i = threadIdx.x; i < NBLOCKS; i += 256) s += g_part[i];
    #pragma unroll
    for (int o = 16; o > 0; o >>= 1) s += __shfl_xor_sync(0xffffffffu, s, o);
    __shared__ float red[8];
    int w = threadIdx.x >> 5;
    if ((threadIdx.x & 31) == 0) red[w] = s;
    __syncthreads();
    if (threadIdx.x < 8) {
        float v = red[threadIdx.x];
        #pragma unroll
        for (int o = 4; o > 0; o >>= 1) v += __shfl_xor_sync(0xffu, v, o);
        if (threadIdx.x == 0) out[0] = v;
    }
}

extern "C" void kernel_launch(void* const* d_in, const int* in_sizes, int n_in,
                              void* d_out, int out_size) {
    const float* counts = (const float*)d_in[0];
    const float* otu    = (const float*)d_in[1];
    const float* comm   = (const float*)d_in[2];
    const float* cw     = (const float*)d_in[3];
    const float* cc     = (const float*)d_in[4];
    const float* gamma  = (const float*)d_in[5];

    prep_kernel<<<(G_*O_*K_ + 255)/256, 256>>>(otu, comm, cw, cc);

    cudaFuncSetAttribute(score_kernel, cudaFuncAttributeMaxDynamicSharedMemorySize,
                         SMEM_BYTES);
    score_kernel<<<dim3(NTILES, G_), NT, SMEM_BYTES>>>(counts, gamma);

    fin_kernel<<<1, 256>>>((float*)d_out);
}